// round 7
// baseline (speedup 1.0000x reference)
#include <cuda_runtime.h>

// Problem constants (fixed by reference)
#define NC       10000
#define ND       1000000
#define B        8192
#define K        64
#define EMB      16
#define CH_DENSE 16
#define DEV_DENSE 20
#define H1       64
#define H2       64
#define ATTN_H   84
#define IN1      32      // CH_DENSE + EMB
#define IN2      132     // DEV_DENSE + 7*EMB

// Scratch
__device__ float g_mean[2 * B * IN2];  // masked-mean features  [2B, 132]
__device__ float g_h[2 * B * H2];      // projected aggregates  [2B, 64]

// ---------------------------------------------------------------------------
// Kernel A: per (vertex, side) neighbor gather + masked mean
//   grid = (B, 2), block = 256 (8 warps). Warp w owns neighbors [8w, 8w+8).
//   Lane roles: 0..27 -> emb float4-group (table j = lane/4, elem (lane%4)*4)
//               28..30 -> dense float4-group lane-28
//               31     -> dense float4-groups 3 and 4
//   No block barrier until the final partial reduce.
// ---------------------------------------------------------------------------
__global__ __launch_bounds__(256)
void agg_mean_kernel(const float* __restrict__ device_dense,   // [ND, 20]
                     const int*   __restrict__ device_cat,     // [ND, 7]
                     const float* __restrict__ lang_emb,
                     const float* __restrict__ plat_emb,
                     const float* __restrict__ os_emb,
                     const float* __restrict__ country_emb,
                     const float* __restrict__ carrier_emb,
                     const float* __restrict__ brand_emb,
                     const float* __restrict__ plat_os_emb,
                     const int*   __restrict__ bot_neibrs,     // [B, K]
                     const int*   __restrict__ normal_neibrs,  // [B, K]
                     const int*   __restrict__ bot_counts,     // [B]
                     const int*   __restrict__ normal_counts)  // [B]
{
    const int b    = blockIdx.x;
    const int side = blockIdx.y;
    const int t    = threadIdx.x;
    const int w    = t >> 5;
    const int lane = t & 31;

    __shared__ __align__(16) float s_part[8][IN2];

    const int* __restrict__ neibrs = side ? normal_neibrs : bot_neibrs;
    const int* __restrict__ counts = side ? normal_counts : bot_counts;

    int cnt = counts[b];
    cnt = cnt < 1 ? 1 : (cnt > K ? K : cnt);

    // preload this warp's 8 neighbor ids into lanes 0..7
    int nb = 0;
    if (lane < 8) nb = neibrs[b * K + w * 8 + lane];

    // lane role setup
    const float* __restrict__ tab = lang_emb;
    int e4 = 0;
    if (lane < 28) {
        const int j = lane >> 2;
        e4 = (lane & 3) << 2;
        switch (j) {
            case 0: tab = lang_emb;    break;
            case 1: tab = plat_emb;    break;
            case 2: tab = os_emb;      break;
            case 3: tab = country_emb; break;
            case 4: tab = carrier_emb; break;
            case 5: tab = brand_emb;   break;
            default: tab = plat_os_emb; break;
        }
    }
    const int j7 = lane >> 2;   // table id (valid for lane<28)

    float4 acc  = make_float4(0.f, 0.f, 0.f, 0.f);
    float4 acc2 = make_float4(0.f, 0.f, 0.f, 0.f);   // lane 31 only

    #pragma unroll
    for (int i = 0; i < 8; ++i) {
        const int  kg    = w * 8 + i;
        const int  nbk   = __shfl_sync(0xffffffffu, nb, i);
        const bool valid = kg < cnt;
        if (lane < 28) {
            if (valid) {
                const int c = device_cat[nbk * 7 + j7];
                const float4 v = *(const float4*)(tab + c * EMB + e4);
                acc.x += v.x; acc.y += v.y; acc.z += v.z; acc.w += v.w;
            }
        } else if (lane < 31) {
            if (valid) {
                const float4 v = *(const float4*)(device_dense + nbk * DEV_DENSE + (lane - 28) * 4);
                acc.x += v.x; acc.y += v.y; acc.z += v.z; acc.w += v.w;
            }
        } else {
            if (valid) {
                const float4 v  = *(const float4*)(device_dense + nbk * DEV_DENSE + 12);
                const float4 v2 = *(const float4*)(device_dense + nbk * DEV_DENSE + 16);
                acc.x  += v.x;  acc.y  += v.y;  acc.z  += v.z;  acc.w  += v.w;
                acc2.x += v2.x; acc2.y += v2.y; acc2.z += v2.z; acc2.w += v2.w;
            }
        }
    }

    // write warp partials (row stride 132 floats = 528B, 16B-divisible)
    float* row = s_part[w];
    if (lane < 28) {
        *(float4*)(row + DEV_DENSE + lane * 4) = acc;
    } else if (lane < 31) {
        *(float4*)(row + (lane - 28) * 4) = acc;
    } else {
        *(float4*)(row + 12) = acc;
        *(float4*)(row + 16) = acc2;
    }
    __syncthreads();

    if (t < IN2) {
        float s = 0.f;
        #pragma unroll
        for (int ww = 0; ww < 8; ++ww) s += s_part[ww][t];
        g_mean[(side * B + b) * IN2 + t] = s / (float)cnt;
    }
}

// ---------------------------------------------------------------------------
// Kernel B: h = mean @ W_agg + b_agg, weights register-cached per block
//   grid = 2048 blocks, 256 threads; each block streams 8 rows (2 per iter)
//   thread role: c = t&63 (output col), ch = t>>6 (one of 4 chunks of 33 i's)
// ---------------------------------------------------------------------------
__global__ __launch_bounds__(256)
void proj_kernel(const float* __restrict__ W_agg,   // [132, 64]
                 const float* __restrict__ b_agg)   // [64]
{
    const int t  = threadIdx.x;
    const int c  = t & 63;
    const int ch = t >> 6;

    __shared__ float s_x[2][IN2];
    __shared__ float s_p[4][2][64];

    float w[33];
    #pragma unroll
    for (int ii = 0; ii < 33; ++ii)
        w[ii] = W_agg[(ch * 33 + ii) * H2 + c];
    const float bias = (t < 128) ? b_agg[c] : 0.f;

    const int r0base = blockIdx.x * 8;
    #pragma unroll
    for (int it = 0; it < 4; ++it) {
        const int r0 = r0base + 2 * it;
        // stage two mean rows (strided: 264 elements over 256 threads)
        for (int i = t; i < 2 * IN2; i += 256) {
            const int r  = (i < IN2) ? 0 : 1;
            const int ci = i - r * IN2;
            s_x[r][ci] = g_mean[(r0 + r) * IN2 + ci];
        }
        __syncthreads();

        float p0 = 0.f, p1 = 0.f;
        #pragma unroll
        for (int ii = 0; ii < 33; ++ii) {
            const float wv = w[ii];
            p0 = fmaf(wv, s_x[0][ch * 33 + ii], p0);
            p1 = fmaf(wv, s_x[1][ch * 33 + ii], p1);
        }
        s_p[ch][0][c] = p0;
        s_p[ch][1][c] = p1;
        __syncthreads();

        if (t < 128) {
            const int r = t >> 6;
            const float h = bias + s_p[0][r][c] + s_p[1][r][c]
                                 + s_p[2][r][c] + s_p[3][r][c];
            g_h[(r0 + r) * H2 + c] = h;
        }
        __syncthreads();
    }
}

// ---------------------------------------------------------------------------
// Kernel C: finalize (attention MLP + softmax2 + combine + self linear)
//   grid = 1024 blocks, 256 threads, 8 vertices per block
//   W_attn register-cached: t<252 : c = t%84, ch = t/84, 32 weights each
//   W_self register-cached: all t : sc = t&63, sch = t>>6, 8 weights each
// ---------------------------------------------------------------------------
__global__ __launch_bounds__(256)
void finalize_kernel(const float* __restrict__ channel_dense,  // [NC, 16]
                     const float* __restrict__ channel_id_emb, // [NC, 16]
                     const float* __restrict__ W_self,         // [32, 64]
                     const float* __restrict__ b_self,         // [64]
                     const float* __restrict__ W_attn,         // [96, 84]
                     const float* __restrict__ b_attn,         // [84]
                     const float* __restrict__ W_attn2,        // [84, 1]
                     const float* __restrict__ b_attn2,        // [1]
                     const int*   __restrict__ channel_ids,    // [NC]
                     const int*   __restrict__ vertices,       // [B]
                     float*       __restrict__ out)            // [B, 128]
{
    const int t = threadIdx.x;

    // attention roles
    const int ac  = (t < 252) ? (t % 84) : 0;
    const int ach = (t < 252) ? (t / 84) : 0;
    // self roles
    const int sc  = t & 63;
    const int sch = t >> 6;

    __shared__ float s_hb[H2];
    __shared__ float s_hn[H2];
    __shared__ float s_chv[IN1];
    __shared__ float s_ap[2][3][84];   // attention partials [group][chunk][col]
    __shared__ float s_r[2][84];       // relu(hidden)*W2
    __shared__ float s_sp[4][64];      // self-linear partials
    __shared__ float s_sc[2];          // scores

    // register-cached weights
    float wa[32];
    if (t < 252) {
        #pragma unroll
        for (int ii = 0; ii < 32; ++ii)
            wa[ii] = W_attn[(ach * 32 + ii) * ATTN_H + ac];
    }
    float ws[8];
    #pragma unroll
    for (int ii = 0; ii < 8; ++ii)
        ws[ii] = W_self[(sch * 8 + ii) * H1 + sc];

    const float rb2  = b_attn2[0];
    const float rba  = (t < 168) ? b_attn[t % 84]  : 0.f;
    const float rw2  = (t < 168) ? W_attn2[t % 84] : 0.f;
    const float rbs  = (t >= 64 && t < 128) ? b_self[t - 64] : 0.f;

    const int bi0 = blockIdx.x * 8;
    #pragma unroll
    for (int it = 0; it < 8; ++it) {
        const int bi = bi0 + it;
        const int v  = vertices[bi];

        // stage inputs
        if (t < H2)                 s_hb[t]        = g_h[bi * H2 + t];
        else if (t < 2 * H2)        s_hn[t - H2]   = g_h[(B + bi) * H2 + (t - H2)];
        else if (t < 2 * H2 + 16)   s_chv[t - 128] = channel_dense[v * CH_DENSE + (t - 128)];
        else if (t < 2 * H2 + 32) {
            const int cid = channel_ids[v];
            s_chv[t - 128] = channel_id_emb[cid * EMB + (t - 144)];
        }
        __syncthreads();

        // attention partials (both groups) + self partials
        if (t < 252) {
            const float* __restrict__ src0 = (ach < 2) ? (s_hb + ach * 32) : s_chv;
            const float* __restrict__ src1 = (ach < 2) ? (s_hn + ach * 32) : s_chv;
            float p0 = 0.f, p1 = 0.f;
            #pragma unroll
            for (int ii = 0; ii < 32; ++ii) {
                const float wv = wa[ii];
                p0 = fmaf(wv, src0[ii], p0);
                p1 = fmaf(wv, src1[ii], p1);
            }
            s_ap[0][ach][ac] = p0;
            s_ap[1][ach][ac] = p1;
        }
        {
            float ps = 0.f;
            #pragma unroll
            for (int ii = 0; ii < 8; ++ii)
                ps = fmaf(ws[ii], s_chv[sch * 8 + ii], ps);
            s_sp[sch][sc] = ps;
        }
        __syncthreads();

        // hidden reduce + relu + *W2
        if (t < 168) {
            const int g = t / 84, c = t % 84;
            const float h = rba + s_ap[g][0][c] + s_ap[g][1][c] + s_ap[g][2][c];
            s_r[g][c] = fmaxf(h, 0.f) * rw2;
        }
        __syncthreads();

        // score reduce over 84 (one warp per group)
        if (t < 64) {
            const int g = t >> 5, lane = t & 31;
            float s = 0.f;
            for (int c = lane; c < ATTN_H; c += 32) s += s_r[g][c];
            #pragma unroll
            for (int off = 16; off > 0; off >>= 1)
                s += __shfl_down_sync(0xffffffffu, s, off);
            if (lane == 0) s_sc[g] = s + rb2;
        }
        __syncthreads();

        // softmax(2) + outputs
        const float m   = fmaxf(s_sc[0], s_sc[1]);
        const float e0  = __expf(s_sc[0] - m);
        const float e1  = __expf(s_sc[1] - m);
        const float inv = 1.f / (e0 + e1);
        const float a0  = e0 * inv, a1 = e1 * inv;

        if (t < H2) {
            out[bi * (H2 + H1) + t] = fmaxf(a0 * s_hb[t] + a1 * s_hn[t], 0.f);
        } else if (t < H2 + H1) {
            const int c = t - H2;
            const float o = rbs + s_sp[0][c] + s_sp[1][c] + s_sp[2][c] + s_sp[3][c];
            out[bi * (H2 + H1) + t] = fmaxf(o, 0.f);
        }
        __syncthreads();
    }
}

// ---------------------------------------------------------------------------
extern "C" void kernel_launch(void* const* d_in, const int* in_sizes, int n_in,
                              void* d_out, int out_size)
{
    const float* channel_dense  = (const float*)d_in[0];
    const float* device_dense   = (const float*)d_in[1];
    const float* channel_id_emb = (const float*)d_in[2];
    const float* lang_emb       = (const float*)d_in[3];
    const float* plat_emb       = (const float*)d_in[4];
    const float* os_emb         = (const float*)d_in[5];
    const float* country_emb    = (const float*)d_in[6];
    const float* carrier_emb    = (const float*)d_in[7];
    const float* brand_emb      = (const float*)d_in[8];
    const float* plat_os_emb    = (const float*)d_in[9];
    const float* W_agg          = (const float*)d_in[10];
    const float* b_agg          = (const float*)d_in[11];
    const float* W_self         = (const float*)d_in[12];
    const float* b_self         = (const float*)d_in[13];
    const float* W_attn         = (const float*)d_in[14];
    const float* b_attn         = (const float*)d_in[15];
    const float* W_attn2        = (const float*)d_in[16];
    const float* b_attn2        = (const float*)d_in[17];
    const int*   channel_ids    = (const int*)d_in[18];
    const int*   device_cat     = (const int*)d_in[19];
    const int*   vertices       = (const int*)d_in[20];
    const int*   bot_neibrs     = (const int*)d_in[21];
    const int*   normal_neibrs  = (const int*)d_in[22];
    const int*   bot_counts     = (const int*)d_in[23];
    const int*   normal_counts  = (const int*)d_in[24];

    float* out = (float*)d_out;

    dim3 gridA(B, 2);
    agg_mean_kernel<<<gridA, 256>>>(device_dense, device_cat,
                                    lang_emb, plat_emb, os_emb, country_emb,
                                    carrier_emb, brand_emb, plat_os_emb,
                                    bot_neibrs, normal_neibrs,
                                    bot_counts, normal_counts);

    proj_kernel<<<2048, 256>>>(W_agg, b_agg);

    finalize_kernel<<<1024, 256>>>(channel_dense, channel_id_emb,
                                   W_self, b_self, W_attn, b_attn,
                                   W_attn2, b_attn2,
                                   channel_ids, vertices, out);
}

// round 15
// speedup vs baseline: 1.8010x; 1.8010x over previous
#include <cuda_runtime.h>

// Problem constants (fixed by reference)
#define NC       10000
#define ND       1000000
#define B        8192
#define K        64
#define EMB      16
#define CH_DENSE 16
#define DEV_DENSE 20
#define H1       64
#define H2       64
#define ATTN_H   84
#define IN1      32      // CH_DENSE + EMB
#define IN2      132     // DEV_DENSE + 7*EMB

// Scratch
__device__ float g_mean[2 * B * IN2];  // masked-mean features  [2B, 132]
__device__ float g_h[2 * B * H2];      // projected aggregates  [2B, 64]

// ---------------------------------------------------------------------------
// Kernel A (v3): per (vertex, side) gather + masked mean.
//   grid = (B, 2), block = 256.
//   Phase-decoupled staging (the measured-fast structure), no div/mod in
//   inner loops, fully-unrolled compile-time k-loops for high MLP.
// ---------------------------------------------------------------------------
__global__ __launch_bounds__(256)
void agg_mean_kernel(const float* __restrict__ device_dense,   // [ND, 20]
                     const int*   __restrict__ device_cat,     // [ND, 7]
                     const float* __restrict__ lang_emb,
                     const float* __restrict__ plat_emb,
                     const float* __restrict__ os_emb,
                     const float* __restrict__ country_emb,
                     const float* __restrict__ carrier_emb,
                     const float* __restrict__ brand_emb,
                     const float* __restrict__ plat_os_emb,
                     const int*   __restrict__ bot_neibrs,     // [B, K]
                     const int*   __restrict__ normal_neibrs,  // [B, K]
                     const int*   __restrict__ bot_counts,     // [B]
                     const int*   __restrict__ normal_counts)  // [B]
{
    const int b    = blockIdx.x;
    const int side = blockIdx.y;
    const int t    = threadIdx.x;

    __shared__ int s_nb[K];
    __shared__ int s_cat[K * 8];                    // rows padded to 8 (shift/and addressing)
    __shared__ __align__(16) float s_epart[8][112]; // emb partials  [kc][feature]
    __shared__ __align__(16) float s_dpart[6][20];  // dense partials[kc][feature]

    const int* __restrict__ neibrs = side ? normal_neibrs : bot_neibrs;
    const int* __restrict__ counts = side ? normal_counts : bot_counts;

    int cnt = counts[b];
    cnt = cnt < 1 ? 1 : (cnt > K ? K : cnt);

    // Phase 1: neighbor ids
    if (t < K) s_nb[t] = neibrs[b * K + t];
    __syncthreads();

    // Phase 2: cat gather — 512 slots (64 rows x 8, col 7 idle), 2 per thread,
    // all loads independent, predicated on validity.
    #pragma unroll
    for (int base = 0; base < 512; base += 256) {
        const int idx = base + t;
        const int k   = idx >> 3;
        const int j   = idx & 7;
        if (j < 7 && k < cnt)
            s_cat[idx] = device_cat[s_nb[k] * 7 + j];
    }
    __syncthreads();

    // Phase 3: accumulate partials
    if (t < 224) {
        const int g  = t % 28;          // one-time div/mod
        const int kc = t / 28;
        const int j  = g >> 2;
        const int e4 = (g & 3) << 2;
        const float* __restrict__ tab;
        switch (j) {
            case 0: tab = lang_emb;    break;
            case 1: tab = plat_emb;    break;
            case 2: tab = os_emb;      break;
            case 3: tab = country_emb; break;
            case 4: tab = carrier_emb; break;
            case 5: tab = brand_emb;   break;
            default: tab = plat_os_emb; break;
        }
        float4 acc = make_float4(0.f, 0.f, 0.f, 0.f);
        #pragma unroll
        for (int k = kc; k < K; k += 8) {           // 8 compile-time iterations
            if (k < cnt) {
                const int c = s_cat[k * 8 + j];     // smem, broadcast-friendly
                const float4 v = *(const float4*)(tab + c * EMB + e4);
                acc.x += v.x; acc.y += v.y; acc.z += v.z; acc.w += v.w;
            }
        }
        *(float4*)(&s_epart[kc][g * 4]) = acc;      // row 448B, 16B-divisible
    } else if (t < 254) {
        const int u  = t - 224;
        const int g  = u % 5;
        const int kc = u / 5;                        // 0..5
        float4 acc = make_float4(0.f, 0.f, 0.f, 0.f);
        #pragma unroll
        for (int k = kc; k < K; k += 6) {            // <= 11 compile-time iterations
            if (k < cnt) {
                const float4 v = *(const float4*)(device_dense + s_nb[k] * DEV_DENSE + g * 4);
                acc.x += v.x; acc.y += v.y; acc.z += v.z; acc.w += v.w;
            }
        }
        *(float4*)(&s_dpart[kc][g * 4]) = acc;       // row 80B, 16B-divisible
    }
    __syncthreads();

    // Phase 4: reduce partials, divide, write mean row
    if (t < IN2) {
        const float inv = 1.f / (float)cnt;
        float s = 0.f;
        if (t < DEV_DENSE) {
            #pragma unroll
            for (int kc = 0; kc < 6; ++kc) s += s_dpart[kc][t];
        } else {
            const int f = t - DEV_DENSE;
            #pragma unroll
            for (int kc = 0; kc < 8; ++kc) s += s_epart[kc][f];
        }
        g_mean[(side * B + b) * IN2 + t] = s * inv;
    }
}

// ---------------------------------------------------------------------------
// Kernel B: h = mean @ W_agg + b_agg, weights register-cached per block
//   grid = 4096 blocks, 256 threads; each block streams 4 rows (2 per iter)
// ---------------------------------------------------------------------------
__global__ __launch_bounds__(256)
void proj_kernel(const float* __restrict__ W_agg,   // [132, 64]
                 const float* __restrict__ b_agg)   // [64]
{
    const int t  = threadIdx.x;
    const int c  = t & 63;
    const int ch = t >> 6;

    __shared__ float s_x[2][IN2];
    __shared__ float s_p[4][2][64];

    float w[33];
    #pragma unroll
    for (int ii = 0; ii < 33; ++ii)
        w[ii] = W_agg[(ch * 33 + ii) * H2 + c];
    const float bias = (t < 128) ? b_agg[c] : 0.f;

    const int r0base = blockIdx.x * 4;
    #pragma unroll
    for (int it = 0; it < 2; ++it) {
        const int r0 = r0base + 2 * it;
        // stage two mean rows (264 elements over 256 threads)
        for (int i = t; i < 2 * IN2; i += 256) {
            const int r  = (i < IN2) ? 0 : 1;
            const int ci = i - r * IN2;
            s_x[r][ci] = g_mean[(r0 + r) * IN2 + ci];
        }
        __syncthreads();

        float p0 = 0.f, p1 = 0.f;
        #pragma unroll
        for (int ii = 0; ii < 33; ++ii) {
            const float wv = w[ii];
            p0 = fmaf(wv, s_x[0][ch * 33 + ii], p0);
            p1 = fmaf(wv, s_x[1][ch * 33 + ii], p1);
        }
        s_p[ch][0][c] = p0;
        s_p[ch][1][c] = p1;
        __syncthreads();

        if (t < 128) {
            const int r = t >> 6;
            const float h = bias + s_p[0][r][c] + s_p[1][r][c]
                                 + s_p[2][r][c] + s_p[3][r][c];
            g_h[(r0 + r) * H2 + c] = h;
        }
        __syncthreads();
    }
}

// ---------------------------------------------------------------------------
// Kernel C: finalize (attention MLP + softmax2 + combine + self linear)
//   grid = 2048 blocks, 256 threads, 4 vertices per block
// ---------------------------------------------------------------------------
__global__ __launch_bounds__(256)
void finalize_kernel(const float* __restrict__ channel_dense,  // [NC, 16]
                     const float* __restrict__ channel_id_emb, // [NC, 16]
                     const float* __restrict__ W_self,         // [32, 64]
                     const float* __restrict__ b_self,         // [64]
                     const float* __restrict__ W_attn,         // [96, 84]
                     const float* __restrict__ b_attn,         // [84]
                     const float* __restrict__ W_attn2,        // [84, 1]
                     const float* __restrict__ b_attn2,        // [1]
                     const int*   __restrict__ channel_ids,    // [NC]
                     const int*   __restrict__ vertices,       // [B]
                     float*       __restrict__ out)            // [B, 128]
{
    const int t = threadIdx.x;

    const int ac  = (t < 252) ? (t % 84) : 0;
    const int ach = (t < 252) ? (t / 84) : 0;
    const int sc  = t & 63;
    const int sch = t >> 6;

    __shared__ float s_hb[H2];
    __shared__ float s_hn[H2];
    __shared__ float s_chv[IN1];
    __shared__ float s_ap[2][3][84];   // attention partials [group][chunk][col]
    __shared__ float s_r[2][84];       // relu(hidden)*W2
    __shared__ float s_sp[4][64];      // self-linear partials
    __shared__ float s_sc[2];          // scores

    float wa[32];
    if (t < 252) {
        #pragma unroll
        for (int ii = 0; ii < 32; ++ii)
            wa[ii] = W_attn[(ach * 32 + ii) * ATTN_H + ac];
    }
    float ws[8];
    #pragma unroll
    for (int ii = 0; ii < 8; ++ii)
        ws[ii] = W_self[(sch * 8 + ii) * H1 + sc];

    const float rb2  = b_attn2[0];
    const float rba  = (t < 168) ? b_attn[t % 84]  : 0.f;
    const float rw2  = (t < 168) ? W_attn2[t % 84] : 0.f;
    const float rbs  = (t >= 64 && t < 128) ? b_self[t - 64] : 0.f;

    const int bi0 = blockIdx.x * 4;
    #pragma unroll
    for (int it = 0; it < 4; ++it) {
        const int bi = bi0 + it;
        const int v  = vertices[bi];

        if (t < H2)                 s_hb[t]        = g_h[bi * H2 + t];
        else if (t < 2 * H2)        s_hn[t - H2]   = g_h[(B + bi) * H2 + (t - H2)];
        else if (t < 2 * H2 + 16)   s_chv[t - 128] = channel_dense[v * CH_DENSE + (t - 128)];
        else if (t < 2 * H2 + 32) {
            const int cid = channel_ids[v];
            s_chv[t - 128] = channel_id_emb[cid * EMB + (t - 144)];
        }
        __syncthreads();

        if (t < 252) {
            const float* __restrict__ src0 = (ach < 2) ? (s_hb + ach * 32) : s_chv;
            const float* __restrict__ src1 = (ach < 2) ? (s_hn + ach * 32) : s_chv;
            float p0 = 0.f, p1 = 0.f;
            #pragma unroll
            for (int ii = 0; ii < 32; ++ii) {
                const float wv = wa[ii];
                p0 = fmaf(wv, src0[ii], p0);
                p1 = fmaf(wv, src1[ii], p1);
            }
            s_ap[0][ach][ac] = p0;
            s_ap[1][ach][ac] = p1;
        }
        {
            float ps = 0.f;
            #pragma unroll
            for (int ii = 0; ii < 8; ++ii)
                ps = fmaf(ws[ii], s_chv[sch * 8 + ii], ps);
            s_sp[sch][sc] = ps;
        }
        __syncthreads();

        if (t < 168) {
            const int g = t / 84, c = t % 84;
            const float h = rba + s_ap[g][0][c] + s_ap[g][1][c] + s_ap[g][2][c];
            s_r[g][c] = fmaxf(h, 0.f) * rw2;
        }
        __syncthreads();

        if (t < 64) {
            const int g = t >> 5, lane = t & 31;
            float s = 0.f;
            for (int c = lane; c < ATTN_H; c += 32) s += s_r[g][c];
            #pragma unroll
            for (int off = 16; off > 0; off >>= 1)
                s += __shfl_down_sync(0xffffffffu, s, off);
            if (lane == 0) s_sc[g] = s + rb2;
        }
        __syncthreads();

        const float m   = fmaxf(s_sc[0], s_sc[1]);
        const float e0  = __expf(s_sc[0] - m);
        const float e1  = __expf(s_sc[1] - m);
        const float inv = 1.f / (e0 + e1);
        const float a0  = e0 * inv, a1 = e1 * inv;

        if (t < H2) {
            out[bi * (H2 + H1) + t] = fmaxf(a0 * s_hb[t] + a1 * s_hn[t], 0.f);
        } else if (t < H2 + H1) {
            const int c = t - H2;
            const float o = rbs + s_sp[0][c] + s_sp[1][c] + s_sp[2][c] + s_sp[3][c];
            out[bi * (H2 + H1) + t] = fmaxf(o, 0.f);
        }
        __syncthreads();
    }
}

// ---------------------------------------------------------------------------
extern "C" void kernel_launch(void* const* d_in, const int* in_sizes, int n_in,
                              void* d_out, int out_size)
{
    const float* channel_dense  = (const float*)d_in[0];
    const float* device_dense   = (const float*)d_in[1];
    const float* channel_id_emb = (const float*)d_in[2];
    const float* lang_emb       = (const float*)d_in[3];
    const float* plat_emb       = (const float*)d_in[4];
    const float* os_emb         = (const float*)d_in[5];
    const float* country_emb    = (const float*)d_in[6];
    const float* carrier_emb    = (const float*)d_in[7];
    const float* brand_emb      = (const float*)d_in[8];
    const float* plat_os_emb    = (const float*)d_in[9];
    const float* W_agg          = (const float*)d_in[10];
    const float* b_agg          = (const float*)d_in[11];
    const float* W_self         = (const float*)d_in[12];
    const float* b_self         = (const float*)d_in[13];
    const float* W_attn         = (const float*)d_in[14];
    const float* b_attn         = (const float*)d_in[15];
    const float* W_attn2        = (const float*)d_in[16];
    const float* b_attn2        = (const float*)d_in[17];
    const int*   channel_ids    = (const int*)d_in[18];
    const int*   device_cat     = (const int*)d_in[19];
    const int*   vertices       = (const int*)d_in[20];
    const int*   bot_neibrs     = (const int*)d_in[21];
    const int*   normal_neibrs  = (const int*)d_in[22];
    const int*   bot_counts     = (const int*)d_in[23];
    const int*   normal_counts  = (const int*)d_in[24];

    float* out = (float*)d_out;

    dim3 gridA(B, 2);
    agg_mean_kernel<<<gridA, 256>>>(device_dense, device_cat,
                                    lang_emb, plat_emb, os_emb, country_emb,
                                    carrier_emb, brand_emb, plat_os_emb,
                                    bot_neibrs, normal_neibrs,
                                    bot_counts, normal_counts);

    proj_kernel<<<4096, 256>>>(W_agg, b_agg);

    finalize_kernel<<<2048, 256>>>(channel_dense, channel_id_emb,
                                   W_self, b_self, W_attn, b_attn,
                                   W_attn2, b_attn2,
                                   channel_ids, vertices, out);
}